// round 4
// baseline (speedup 1.0000x reference)
#include <cuda_runtime.h>
#include <cuda_bf16.h>
#include <cstdint>

// Problem constants
#define NPIX   65536      // 64 * 32 * 32 pixels
#define HW     1024       // 32*32
#define CCH    10         // channels / token bits
#define NCODE  1024       // 2^10
#define NELEM  655360     // 64*10*32*32

// Output layout (flattened reference tuple, fp32)
#define OUT_SCALARS 655360
#define OUT_IDX     655365

// 400 * log2(e)
#define CQ  577.0780163555854f
#define LN2 0.69314718055994531f

// Fused launch shape
#define SBLK 256                      // sign/index blocks (1 px / thread)
#define EBLK 592                      // entropy blocks
#define TOTALBLK (SBLK + EBLK)        // 848
#define THR  256
#define EWPB 8
#define NWARPS (EBLK * EWPB)          // 4736 entropy warps, grid-stride pixels

// Scratch (static __device__ — no allocations). Zero at module load;
// the finalizing block re-zeros everything at the end of every launch.
__device__ float g_avg_probs[NCODE];
__device__ float g_pse_sum;
__device__ float g_commit_sum;
__device__ unsigned int g_done;

// ---------------- packed fp32 helpers (Blackwell f32x2) ----------------
__device__ __forceinline__ unsigned long long pk2(float a, float b) {
    unsigned long long r;
    asm("mov.b64 %0, {%1, %2};" : "=l"(r) : "f"(a), "f"(b));
    return r;
}
__device__ __forceinline__ void upk2(unsigned long long v, float& a, float& b) {
    asm("mov.b64 {%0, %1}, %2;" : "=f"(a), "=f"(b) : "l"(v));
}
__device__ __forceinline__ void ffma2(unsigned long long& acc,
                                      unsigned long long a, unsigned long long b) {
    asm("fma.rn.f32x2 %0, %1, %2, %0;" : "+l"(acc) : "l"(a), "l"(b));
}
__device__ __forceinline__ float ex2f(float x) {
    float r; asm("ex2.approx.f32 %0, %1;" : "=f"(r) : "f"(x)); return r;
}
__device__ __forceinline__ float rcpf(float x) {
    float r; asm("rcp.approx.f32 %0, %1;" : "=f"(r) : "f"(x)); return r;
}

// ---------------------------------------------------------------------------
// One fused kernel. Blocks [0,SBLK): signs/indices/commitment.
// Blocks [SBLK,TOTALBLK): entropy (rank-1 softmax factorization).
// Last block to finish finalizes the scalars and re-zeros scratch.
// ---------------------------------------------------------------------------
__global__ __launch_bounds__(THR, 3) void lfq_fused_kernel(
    const float* __restrict__ z, float* __restrict__ out)
{
    __shared__ float s_ap[NCODE];
    __shared__ __align__(16) float s_x[EWPB][32];
    __shared__ float s_red[EWPB];
    __shared__ unsigned int s_flag;

    int tid  = threadIdx.x;
    int lane = tid & 31;
    int w    = tid >> 5;

    if (blockIdx.x < SBLK) {
        // ---------------- sign / index / commitment ----------------
        int p  = blockIdx.x * THR + tid;          // one pixel per thread
        int b  = p >> 10;
        int hw = p & (HW - 1);
        const float* zp = z   + b * (CCH * HW) + hw;
        float*       op = out + b * (CCH * HW) + hw;

        int   idx  = 0;
        float csum = 0.0f;
#pragma unroll
        for (int c = 0; c < CCH; c++) {
            float v = __ldg(zp + c * HW);
            bool pos = v > 0.0f;
            op[c * HW] = pos ? 1.0f : -1.0f;
            idx |= (pos ? 1 : 0) << c;
            float d = 1.0f - fabsf(v);
            csum = fmaf(d, d, csum);
        }
        out[OUT_IDX + p] = (float)idx;

#pragma unroll
        for (int o = 16; o; o >>= 1)
            csum += __shfl_xor_sync(0xFFFFFFFFu, csum, o);
        if (lane == 0) s_red[w] = csum;
        __syncthreads();
        if (tid == 0) {
            float v = 0.0f;
#pragma unroll
            for (int i = 0; i < EWPB; i++) v += s_red[i];
            atomicAdd(&g_commit_sum, v);
        }
    } else {
        // ---------------- entropy ----------------
        for (int i = tid; i < NCODE; i += THR) s_ap[i] = 0.0f;
        __syncthreads();

        // per-lane sign constants: lane bit (c%5) decides match direction
        float sgn[CCH];
#pragma unroll
        for (int c = 0; c < CCH; c++)
            sgn[c] = ((lane >> (c % 5)) & 1) ? CQ : -CQ;

        unsigned long long ap2[16];
#pragma unroll
        for (int k = 0; k < 16; k++) ap2[k] = 0ULL;
        float pse = 0.0f;

        int wid = (blockIdx.x - SBLK) * EWPB + w;
        for (int p = wid; p < NPIX; p += NWARPS) {
            int b  = p >> 10;
            int hw = p & (HW - 1);
            const float* zp = z + b * (CCH * HW) + hw;

            float b2 = 0.0f, g2 = 0.0f;
#pragma unroll
            for (int c = 0; c < 5; c++) {
                float t = __ldg(zp + c * HW) * sgn[c];
                b2 += fminf(t, 0.0f);
            }
#pragma unroll
            for (int c = 5; c < CCH; c++) {
                float t = __ldg(zp + c * HW) * sgn[c];
                g2 += fminf(t, 0.0f);
            }

            float eb = ex2f(b2);          // lane as lo-half of code
            float Eh = ex2f(g2);          // lane as hi-half of code
            float p1 = eb * b2;
            float p2 = Eh * g2;

            float SB = eb, SE = Eh, S1 = p1, S2 = p2;
#pragma unroll
            for (int o = 16; o; o >>= 1) {
                SB += __shfl_xor_sync(0xFFFFFFFFu, SB, o);
                SE += __shfl_xor_sync(0xFFFFFFFFu, SE, o);
                S1 += __shfl_xor_sync(0xFFFFFFFFu, S1, o);
                S2 += __shfl_xor_sync(0xFFFFFFFFu, S2, o);
            }

            float Z    = SB * SE;                 // >= 1 (max term is exp(0))
            float s    = fmaf(SB, SE, -1.0f);     // Z - 1 >= 0
            float invZ = rcpf(Z);
            float T2   = fmaf(S1, SE, SB * S2);   // sum e * (delta*log2e)

            float lg;                             // ln(Z)
            if (s < 0.0625f)
                lg = s * (1.0f + s * (-0.5f + s * (0.33333334f + s * -0.25f)));
            else
                lg = logf(Z);
            pse += lg - LN2 * T2 * invZ;

            // avg_probs rank-1 accumulate: ap[lane][j] += (eb*invZ) * Eh_j
            float u = eb * invZ;
            s_x[w][lane] = Eh;
            __syncwarp();
            unsigned long long u2 = pk2(u, u);
            const unsigned long long* xq = (const unsigned long long*)s_x[w];
#pragma unroll
            for (int k = 0; k < 16; k++) ffma2(ap2[k], u2, xq[k]);
            __syncwarp();
        }

        if (lane == 0) atomicAdd(&g_pse_sum, pse);

        // flush avg_probs: smem atomics (bank = lane, conflict-free) -> global
#pragma unroll
        for (int k = 0; k < 16; k++) {
            float a, bv; upk2(ap2[k], a, bv);
            atomicAdd(&s_ap[(2 * k)     * 32 + lane], a);
            atomicAdd(&s_ap[(2 * k + 1) * 32 + lane], bv);
        }
        __syncthreads();
        for (int i = tid; i < NCODE; i += THR)
            atomicAdd(&g_avg_probs[i], s_ap[i]);
    }

    // ---------------- last-block finalize ----------------
    __syncthreads();
    if (tid == 0) {
        __threadfence();
        s_flag = (atomicAdd(&g_done, 1u) == TOTALBLK - 1) ? 1u : 0u;
    }
    __syncthreads();
    if (s_flag) {
        // All producer updates were global atomics (L2-resident); read via .cg.
        float local = 0.0f;
        for (int i = tid; i < NCODE; i += THR) {
            float ap = __ldcg(&g_avg_probs[i]) * (1.0f / (float)NPIX);
            local += ap * __logf(ap + 1e-5f);
        }
#pragma unroll
        for (int o = 16; o; o >>= 1)
            local += __shfl_xor_sync(0xFFFFFFFFu, local, o);
        if (lane == 0) s_red[w] = local;
        __syncthreads();
        if (tid == 0) {
            float v = 0.0f;
#pragma unroll
            for (int i = 0; i < EWPB; i++) v += s_red[i];
            float avg_ent = -v;
            float pse     = __ldcg(&g_pse_sum) * (1.0f / (float)NPIX);
            float commit  = 0.25f * __ldcg(&g_commit_sum) * (1.0f / (float)NELEM);
            float ent_l   = 0.1f * (pse - avg_ent);
            out[OUT_SCALARS + 0] = commit + ent_l;   // loss
            out[OUT_SCALARS + 1] = commit;           // commitment_loss
            out[OUT_SCALARS + 2] = ent_l;            // entropy_loss
            out[OUT_SCALARS + 3] = pse;              // per_sample_entropy
            out[OUT_SCALARS + 4] = avg_ent;          // avg_entropy
        }
        // Re-zero scratch for the next graph replay (deterministic state).
        for (int i = tid; i < NCODE; i += THR) __stcg(&g_avg_probs[i], 0.0f);
        if (tid == 0) {
            __stcg(&g_pse_sum, 0.0f);
            __stcg(&g_commit_sum, 0.0f);
            __threadfence();
            atomicExch(&g_done, 0u);
        }
    }
}

// ---------------------------------------------------------------------------
extern "C" void kernel_launch(void* const* d_in, const int* in_sizes, int n_in,
                              void* d_out, int out_size)
{
    const float* z   = (const float*)d_in[0];
    float*       out = (float*)d_out;
    (void)in_sizes; (void)n_in; (void)out_size;  // codebook implicit

    lfq_fused_kernel<<<TOTALBLK, THR>>>(z, out);
}

// round 10
// speedup vs baseline: 1.1139x; 1.1139x over previous
#include <cuda_runtime.h>
#include <cuda_bf16.h>
#include <cstdint>

// Problem constants
#define NPIX   65536      // 64 * 32 * 32 pixels
#define HW     1024       // 32*32
#define CCH    10         // channels / token bits
#define NCODE  1024       // 2^10
#define NELEM  655360     // 64*10*32*32

// Output layout (flattened reference tuple, fp32)
#define OUT_SCALARS 655360
#define OUT_IDX     655365

// 400 * log2(e)
#define CQ  577.0780163555854f
#define LN2 0.69314718055994531f

// Launch shapes
#define ABLK 256                      // signidx: 1 px / thread
#define ATHR 256
#define EBLK 444                      // entropy: 3 CTAs/SM on 148 SMs
#define ETHR 256
#define EWPB 8
#define NEWARPS (EBLK * EWPB)         // 3552 warps, grid-stride over pixels

// Scratch (static __device__ — no allocations). Zero at module load;
// the finalizing block re-zeros for the next graph replay.
__device__ float g_avg_probs[NCODE];
__device__ float g_pse_sum;
__device__ float g_commit_parts[ABLK];
__device__ unsigned int g_done;

// ---------------- helpers ----------------
__device__ __forceinline__ void wred2(float& a, float& b) {   // 2-value butterfly
#pragma unroll
    for (int o = 16; o; o >>= 1) {
        a += __shfl_xor_sync(0xFFFFFFFFu, a, o);
        b += __shfl_xor_sync(0xFFFFFFFFu, b, o);
    }
}
__device__ __forceinline__ float wred1(float a) {
#pragma unroll
    for (int o = 16; o; o >>= 1)
        a += __shfl_xor_sync(0xFFFFFFFFu, a, o);
    return a;
}
__device__ __forceinline__ unsigned long long pk2(float a, float b) {
    unsigned long long r;
    asm("mov.b64 %0, {%1, %2};" : "=l"(r) : "f"(a), "f"(b));
    return r;
}
__device__ __forceinline__ void upk2(unsigned long long v, float& a, float& b) {
    asm("mov.b64 {%0, %1}, %2;" : "=f"(a), "=f"(b) : "l"(v));
}
__device__ __forceinline__ void ffma2(unsigned long long& acc,
                                      unsigned long long a, unsigned long long b) {
    asm("fma.rn.f32x2 %0, %1, %2, %0;" : "+l"(acc) : "l"(a), "l"(b));
}
__device__ __forceinline__ float ex2f(float x) {
    float r; asm("ex2.approx.f32 %0, %1;" : "=f"(r) : "f"(x)); return r;
}
__device__ __forceinline__ float rcpf(float x) {
    float r; asm("rcp.approx.f32 %0, %1;" : "=f"(r) : "f"(x)); return r;
}

// ---------------------------------------------------------------------------
// Kernel A: signs, indices, commitment partials. Block 0 zeros entropy scratch.
// ---------------------------------------------------------------------------
__global__ __launch_bounds__(ATHR) void lfq_signidx_kernel(
    const float* __restrict__ z, float* __restrict__ out)
{
    int tid = threadIdx.x;
    if (blockIdx.x == 0) {
        for (int i = tid; i < NCODE; i += ATHR) g_avg_probs[i] = 0.0f;
        if (tid == 0) g_pse_sum = 0.0f;
    }

    int p  = blockIdx.x * ATHR + tid;
    int b  = p >> 10;
    int hw = p & (HW - 1);
    const float* zp = z   + b * (CCH * HW) + hw;
    float*       op = out + b * (CCH * HW) + hw;

    int   idx  = 0;
    float csum = 0.0f;
#pragma unroll
    for (int c = 0; c < CCH; c++) {
        float v = __ldg(zp + c * HW);
        bool pos = v > 0.0f;
        op[c * HW] = pos ? 1.0f : -1.0f;
        idx |= (pos ? 1 : 0) << c;
        float d = 1.0f - fabsf(v);
        csum = fmaf(d, d, csum);
    }
    out[OUT_IDX + p] = (float)idx;

    csum = wred1(csum);
    __shared__ float s_red[ATHR / 32];
    if ((tid & 31) == 0) s_red[tid >> 5] = csum;
    __syncthreads();
    if (tid == 0) {
        float v = 0.0f;
#pragma unroll
        for (int w = 0; w < ATHR / 32; w++) v += s_red[w];
        g_commit_parts[blockIdx.x] = v;      // plain overwrite, no init needed
    }
}

// ---------------------------------------------------------------------------
// Kernel B: entropy (rank-1 softmax factorization) + last-block finalize.
//   code n = lo + 32*hi;  delta_n*log2e = b2[lo] + g2[hi], both <= 0, max 0
//   e_n = eb_lo * Eh_hi;  Z = SB*SE
//   T2/Z = S1/SB + S2/SE  -> per-lane deferred accumulation (x1, x2):
//   only SB,SE need a per-pixel warp reduction.
// ---------------------------------------------------------------------------
__global__ __launch_bounds__(ETHR, 3) void lfq_entropy_kernel(
    const float* __restrict__ z, float* __restrict__ out)
{
    __shared__ float s_ap[NCODE];
    __shared__ __align__(16) float s_x[EWPB][32];
    __shared__ float s_fred[EWPB];
    __shared__ float s_cred[EWPB];
    __shared__ unsigned int s_flag;

    int tid  = threadIdx.x;
    int lane = tid & 31;
    int w    = tid >> 5;
    for (int i = tid; i < NCODE; i += ETHR) s_ap[i] = 0.0f;
    __syncthreads();

    // per-lane sign constants: lane bit (c%5) decides match direction
    float sgn[CCH];
#pragma unroll
    for (int c = 0; c < CCH; c++)
        sgn[c] = ((lane >> (c % 5)) & 1) ? CQ : -CQ;

    unsigned long long ap2[16];
#pragma unroll
    for (int k = 0; k < 16; k++) ap2[k] = 0ULL;
    float pse_lg = 0.0f;           // sum of ln(Z) terms (lane-uniform)
    float x1 = 0.0f, x2 = 0.0f;    // per-lane deferred S1/SB, S2/SE partials

    int wid = blockIdx.x * EWPB + w;
    for (int p = wid; p < NPIX; p += NEWARPS) {
        int b  = p >> 10;
        int hw = p & (HW - 1);
        const float* zp = z + b * (CCH * HW) + hw;

        float b2 = 0.0f, g2 = 0.0f;
#pragma unroll
        for (int c = 0; c < 5; c++) {
            float t = __ldg(zp + c * HW) * sgn[c];
            b2 += fminf(t, 0.0f);
        }
#pragma unroll
        for (int c = 5; c < CCH; c++) {
            float t = __ldg(zp + c * HW) * sgn[c];
            g2 += fminf(t, 0.0f);
        }

        float eb = ex2f(b2);              // lane as lo-half of code
        float Eh = ex2f(g2);              // lane as hi-half of code

        float SB = eb, SE = Eh;
        wred2(SB, SE);                    // the only per-pixel reduction

        float rSB  = rcpf(SB);
        float rSE  = rcpf(SE);
        float invZ = rSB * rSE;
        float s    = fmaf(SB, SE, -1.0f); // Z - 1 >= 0 (max term is exp(0))

        float lg;                          // ln(Z)
        if (s < 0.0625f)
            lg = s * (1.0f + s * (-0.5f + s * (0.33333334f + s * -0.25f)));
        else
            lg = logf(SB * SE);
        pse_lg += lg;

        // deferred: T2/Z = S1/SB + S2/SE; accumulate per-lane, reduce once later
        x1 = fmaf(eb * b2, rSB, x1);
        x2 = fmaf(Eh * g2, rSE, x2);

        // avg_probs rank-1 accumulate: ap[lane][j] += (eb*invZ) * Eh_j
        float u = eb * invZ;
        s_x[w][lane] = Eh;
        __syncwarp();
        unsigned long long u2 = pk2(u, u);
        const unsigned long long* xq = (const unsigned long long*)s_x[w];
#pragma unroll
        for (int k = 0; k < 16; k++) ffma2(ap2[k], u2, xq[k]);
        __syncwarp();
    }

    // fold deferred partials: pse contribution = sum lg - LN2*(X1 + X2)
    wred2(x1, x2);
    if (lane == 0)
        atomicAdd(&g_pse_sum, pse_lg - LN2 * (x1 + x2));

    // flush avg_probs: smem atomics (bank = lane, conflict-free) -> global
#pragma unroll
    for (int k = 0; k < 16; k++) {
        float a, bv; upk2(ap2[k], a, bv);
        atomicAdd(&s_ap[(2 * k)     * 32 + lane], a);
        atomicAdd(&s_ap[(2 * k + 1) * 32 + lane], bv);
    }
    __syncthreads();
    for (int i = tid; i < NCODE; i += ETHR)
        atomicAdd(&g_avg_probs[i], s_ap[i]);

    // ---------------- last-block finalize ----------------
    __syncthreads();
    if (tid == 0) {
        __threadfence();
        s_flag = (atomicAdd(&g_done, 1u) == EBLK - 1) ? 1u : 0u;
    }
    __syncthreads();
    if (s_flag) {
        // avg_entropy (producers used global atomics -> L2-coherent .cg reads)
        float local = 0.0f;
        for (int i = tid; i < NCODE; i += ETHR) {
            float ap = __ldcg(&g_avg_probs[i]) * (1.0f / (float)NPIX);
            local += ap * __logf(ap + 1e-5f);
        }
        local = wred1(local);
        if (lane == 0) s_fred[w] = local;
        // commitment partials (written by signidx kernel, prior launch)
        float cpart = 0.0f;
        for (int i = tid; i < ABLK; i += ETHR) cpart += g_commit_parts[i];
        cpart = wred1(cpart);
        if (lane == 0) s_cred[w] = cpart;
        __syncthreads();
        if (tid == 0) {
            float v = 0.0f, cs = 0.0f;
#pragma unroll
            for (int i = 0; i < EWPB; i++) { v += s_fred[i]; cs += s_cred[i]; }
            float avg_ent = -v;
            float pse_m   = __ldcg(&g_pse_sum) * (1.0f / (float)NPIX);
            float commit  = 0.25f * cs * (1.0f / (float)NELEM);
            float ent_l   = 0.1f * (pse_m - avg_ent);
            out[OUT_SCALARS + 0] = commit + ent_l;   // loss
            out[OUT_SCALARS + 1] = commit;           // commitment_loss
            out[OUT_SCALARS + 2] = ent_l;            // entropy_loss
            out[OUT_SCALARS + 3] = pse_m;            // per_sample_entropy
            out[OUT_SCALARS + 4] = avg_ent;          // avg_entropy
        }
        // reset scratch for next graph replay
        for (int i = tid; i < NCODE; i += ETHR) __stcg(&g_avg_probs[i], 0.0f);
        if (tid == 0) {
            __stcg(&g_pse_sum, 0.0f);
            __threadfence();
            atomicExch(&g_done, 0u);
        }
    }
}

// ---------------------------------------------------------------------------
extern "C" void kernel_launch(void* const* d_in, const int* in_sizes, int n_in,
                              void* d_out, int out_size)
{
    const float* z   = (const float*)d_in[0];
    float*       out = (float*)d_out;
    (void)in_sizes; (void)n_in; (void)out_size;  // codebook implicit

    lfq_signidx_kernel<<<ABLK, ATHR>>>(z, out);
    lfq_entropy_kernel<<<EBLK, ETHR>>>(z, out);
}

// round 12
// speedup vs baseline: 1.3227x; 1.1875x over previous
#include <cuda_runtime.h>
#include <cuda_bf16.h>
#include <cstdint>

// Problem constants
#define NPIX   65536      // 64 * 32 * 32 pixels
#define HW     1024       // 32*32
#define CCH    10         // channels / token bits
#define NCODE  1024       // 2^10
#define NELEM  655360     // 64*10*32*32

// Output layout (flattened reference tuple, fp32)
#define OUT_SCALARS 655360
#define OUT_IDX     655365

// CQ = 400*log2(e);  CQH = CQ/2 (dot-trick halves the coefficient)
#define CQ   577.0780163555854f
#define CQH  288.5390081777927f
#define LN2  0.69314718055994531f

// Launch shapes
#define ABLK 256                      // signidx: 1 px / thread
#define ATHR 256
#define EBLK 444                      // entropy: 3 CTAs/SM on 148 SMs
#define ETHR 256
#define EWPB 8
#define NEWARPS (EBLK * EWPB)         // 3552 warps; grid-stride over pixel PAIRS

typedef unsigned long long ull;

// Scratch (static __device__ — no allocations). Zero at module load;
// the finalizing block re-zeros for the next graph replay.
__device__ float g_avg_probs[NCODE];
__device__ float g_pse_sum;
__device__ float g_commit_parts[ABLK];
__device__ unsigned int g_done;

// ---------------- helpers ----------------
__device__ __forceinline__ float wred1(float a) {
#pragma unroll
    for (int o = 16; o; o >>= 1)
        a += __shfl_xor_sync(0xFFFFFFFFu, a, o);
    return a;
}
__device__ __forceinline__ void wred2(float& a, float& b) {
#pragma unroll
    for (int o = 16; o; o >>= 1) {
        a += __shfl_xor_sync(0xFFFFFFFFu, a, o);
        b += __shfl_xor_sync(0xFFFFFFFFu, b, o);
    }
}
__device__ __forceinline__ void wred4(float& a, float& b, float& c, float& d) {
#pragma unroll
    for (int o = 16; o; o >>= 1) {   // 4 interleaved chains: latencies overlap
        a += __shfl_xor_sync(0xFFFFFFFFu, a, o);
        b += __shfl_xor_sync(0xFFFFFFFFu, b, o);
        c += __shfl_xor_sync(0xFFFFFFFFu, c, o);
        d += __shfl_xor_sync(0xFFFFFFFFu, d, o);
    }
}
__device__ __forceinline__ ull pk2(float a, float b) {
    ull r; asm("mov.b64 %0, {%1, %2};" : "=l"(r) : "f"(a), "f"(b)); return r;
}
__device__ __forceinline__ void upk2(ull v, float& a, float& b) {
    asm("mov.b64 {%0, %1}, %2;" : "=f"(a), "=f"(b) : "l"(v));
}
__device__ __forceinline__ ull addp(ull a, ull b) {
    ull r; asm("add.rn.f32x2 %0, %1, %2;" : "=l"(r) : "l"(a), "l"(b)); return r;
}
__device__ __forceinline__ ull mulp(ull a, ull b) {
    ull r; asm("mul.rn.f32x2 %0, %1, %2;" : "=l"(r) : "l"(a), "l"(b)); return r;
}
__device__ __forceinline__ ull fmap(ull a, ull b, ull c) {
    ull r; asm("fma.rn.f32x2 %0, %1, %2, %3;" : "=l"(r) : "l"(a), "l"(b), "l"(c)); return r;
}
__device__ __forceinline__ void ffma2(ull& acc, ull a, ull b) {
    asm("fma.rn.f32x2 %0, %1, %2, %0;" : "+l"(acc) : "l"(a), "l"(b));
}
__device__ __forceinline__ ull absp(ull v) { return v & 0x7FFFFFFF7FFFFFFFULL; }
__device__ __forceinline__ float ex2f(float x) {
    float r; asm("ex2.approx.f32 %0, %1;" : "=f"(r) : "f"(x)); return r;
}
__device__ __forceinline__ float rcpf(float x) {
    float r; asm("rcp.approx.f32 %0, %1;" : "=f"(r) : "f"(x)); return r;
}

// ---------------------------------------------------------------------------
// Kernel A: signs, indices, commitment partials. Block 0 zeros entropy scratch.
// ---------------------------------------------------------------------------
__global__ __launch_bounds__(ATHR) void lfq_signidx_kernel(
    const float* __restrict__ z, float* __restrict__ out)
{
    int tid = threadIdx.x;
    if (blockIdx.x == 0) {
        for (int i = tid; i < NCODE; i += ATHR) g_avg_probs[i] = 0.0f;
        if (tid == 0) g_pse_sum = 0.0f;
    }

    int p  = blockIdx.x * ATHR + tid;
    int b  = p >> 10;
    int hw = p & (HW - 1);
    const float* zp = z   + b * (CCH * HW) + hw;
    float*       op = out + b * (CCH * HW) + hw;

    int   idx  = 0;
    float csum = 0.0f;
#pragma unroll
    for (int c = 0; c < CCH; c++) {
        float v = __ldg(zp + c * HW);
        bool pos = v > 0.0f;
        op[c * HW] = pos ? 1.0f : -1.0f;
        idx |= (pos ? 1 : 0) << c;
        float d = 1.0f - fabsf(v);
        csum = fmaf(d, d, csum);
    }
    out[OUT_IDX + p] = (float)idx;

    csum = wred1(csum);
    __shared__ float s_red[ATHR / 32];
    if ((tid & 31) == 0) s_red[tid >> 5] = csum;
    __syncthreads();
    if (tid == 0) {
        float v = 0.0f;
#pragma unroll
        for (int w = 0; w < ATHR / 32; w++) v += s_red[w];
        g_commit_parts[blockIdx.x] = v;
    }
}

// ---------------------------------------------------------------------------
// Kernel B: entropy, 2 pixels (a pair) per iteration, packed f32x2 math.
//   code n = lo + 32*hi;  delta_n*log2e = b2[lo] + g2[hi], both <= 0, max 0
//   b2 = sum_c min(+-CQ*z_c, 0) = sum_c (+-CQH)*z_c - CQH*sum|z_c|  (dot trick)
//   Z = SB*SE;  T2/Z = S1/SB + S2/SE (deferred per-lane accumulation)
// ---------------------------------------------------------------------------
__global__ __launch_bounds__(ETHR, 3) void lfq_entropy_kernel(
    const float* __restrict__ z, float* __restrict__ out)
{
    __shared__ float s_ap[NCODE];
    __shared__ __align__(16) float s_x[EWPB][2][2][32];  // [warp][parity][A/B][lane]
    __shared__ float s_fred[EWPB];
    __shared__ float s_cred[EWPB];
    __shared__ unsigned int s_flag;

    int tid  = threadIdx.x;
    int lane = tid & 31;
    int w    = tid >> 5;
    for (int i = tid; i < NCODE; i += ETHR) s_ap[i] = 0.0f;
    __syncthreads();

    // packed per-lane sign constants: lane bit c picks +-CQH (same for c and c+5)
    ull sgn2[5];
#pragma unroll
    for (int c = 0; c < 5; c++) {
        float s = ((lane >> c) & 1) ? CQH : -CQH;
        sgn2[c] = pk2(s, s);
    }
    const ull NCQH2 = pk2(-CQH, -CQH);

    ull ap2[16];
#pragma unroll
    for (int k = 0; k < 16; k++) ap2[k] = 0ULL;
    float pse_lg = 0.0f;            // sum of ln(Z) (lane-uniform)
    ull x1_2 = 0ULL, x2_2 = 0ULL;   // packed deferred S1/SB, S2/SE partials
    int par = 0;

    int wid = blockIdx.x * EWPB + w;
    for (int q = wid; q < NPIX / 2; q += NEWARPS, par ^= 1) {
        int p0 = q << 1;                      // pixels p0, p0+1 (same batch row)
        int b  = p0 >> 10;
        int hw = p0 & (HW - 1);               // even -> float2 aligned
        const float2* zp = (const float2*)(z + b * (CCH * HW) + hw);

        ull dotL = 0ULL, dotH = 0ULL, AL = 0ULL, AH = 0ULL;
#pragma unroll
        for (int c = 0; c < 5; c++) {
            float2 v = __ldg(zp + c * (HW / 2));
            ull v2 = pk2(v.x, v.y);
            dotL = fmap(v2, sgn2[c], dotL);
            AL   = addp(AL, absp(v2));
        }
#pragma unroll
        for (int c = 0; c < 5; c++) {
            float2 v = __ldg(zp + (c + 5) * (HW / 2));
            ull v2 = pk2(v.x, v.y);
            dotH = fmap(v2, sgn2[c], dotH);
            AH   = addp(AH, absp(v2));
        }

        ull b22 = fmap(AL, NCQH2, dotL);      // (b2A, b2B), both <= 0
        ull g22 = fmap(AH, NCQH2, dotH);      // (g2A, g2B)

        float b2A, b2B, g2A, g2B;
        upk2(b22, b2A, b2B);
        upk2(g22, g2A, g2B);
        float ebA = ex2f(b2A), ebB = ex2f(b2B);
        float EhA = ex2f(g2A), EhB = ex2f(g2B);

        float SBA = ebA, SEA = EhA, SBB = ebB, SEB = EhB;
        wred4(SBA, SEA, SBB, SEB);            // two pixels' chains overlap

        float rSBA = rcpf(SBA), rSEA = rcpf(SEA);
        float rSBB = rcpf(SBB), rSEB = rcpf(SEB);
        float sA = fmaf(SBA, SEA, -1.0f);     // Z - 1 >= 0 (max term = exp(0))
        float sB = fmaf(SBB, SEB, -1.0f);

        if (fmaxf(sA, sB) < 0.0625f) {        // ln(1+s), FFMA-imm polynomial
            float tA = fmaf(sA, -0.25f, 0.33333334f);
            float tB = fmaf(sB, -0.25f, 0.33333334f);
            tA = fmaf(sA, tA, -0.5f);  tB = fmaf(sB, tB, -0.5f);
            tA = fmaf(sA, tA, 1.0f);   tB = fmaf(sB, tB, 1.0f);
            pse_lg += sA * tA + sB * tB;
        } else {
            pse_lg += logf(SBA * SEA) + logf(SBB * SEB);
        }

        // deferred: T2/Z = S1/SB + S2/SE, accumulated per-lane, packed A/B
        ull eb2  = pk2(ebA, ebB), Eh2  = pk2(EhA, EhB);
        ull rSB2 = pk2(rSBA, rSBB), rSE2 = pk2(rSEA, rSEB);
        x1_2 = fmap(mulp(eb2, b22), rSB2, x1_2);
        x2_2 = fmap(mulp(Eh2, g22), rSE2, x2_2);

        float uA = ebA * (rSBA * rSEA);       // eb * invZ
        float uB = ebB * (rSBB * rSEB);

        // avg_probs rank-1: ap[lane][j] += uA*EhA_j + uB*EhB_j
        s_x[w][par][0][lane] = EhA;
        s_x[w][par][1][lane] = EhB;
        __syncwarp();
        ull uA2 = pk2(uA, uA), uB2 = pk2(uB, uB);
        const ull* xa = (const ull*)s_x[w][par][0];
        const ull* xb = (const ull*)s_x[w][par][1];
#pragma unroll
        for (int k = 0; k < 16; k++) {
            ffma2(ap2[k], uA2, xa[k]);
            ffma2(ap2[k], uB2, xb[k]);
        }
        // no trailing syncwarp: parity double-buffer protects next iteration
    }

    // fold deferred partials: pse contribution = sum lg - LN2*(X1 + X2)
    float x1a, x1b, x2a, x2b;
    upk2(x1_2, x1a, x1b);
    upk2(x2_2, x2a, x2b);
    float x1 = x1a + x1b, x2 = x2a + x2b;
    wred2(x1, x2);
    if (lane == 0)
        atomicAdd(&g_pse_sum, pse_lg - LN2 * (x1 + x2));

    // flush avg_probs: smem atomics (bank = lane, conflict-free) -> global
#pragma unroll
    for (int k = 0; k < 16; k++) {
        float a, bv; upk2(ap2[k], a, bv);
        atomicAdd(&s_ap[(2 * k)     * 32 + lane], a);
        atomicAdd(&s_ap[(2 * k + 1) * 32 + lane], bv);
    }
    __syncthreads();
    for (int i = tid; i < NCODE; i += ETHR)
        atomicAdd(&g_avg_probs[i], s_ap[i]);

    // ---------------- last-block finalize ----------------
    __syncthreads();
    if (tid == 0) {
        __threadfence();
        s_flag = (atomicAdd(&g_done, 1u) == EBLK - 1) ? 1u : 0u;
    }
    __syncthreads();
    if (s_flag) {
        float local = 0.0f;
        for (int i = tid; i < NCODE; i += ETHR) {
            float ap = __ldcg(&g_avg_probs[i]) * (1.0f / (float)NPIX);
            local += ap * __logf(ap + 1e-5f);
        }
        local = wred1(local);
        if (lane == 0) s_fred[w] = local;
        float cpart = 0.0f;
        for (int i = tid; i < ABLK; i += ETHR) cpart += g_commit_parts[i];
        cpart = wred1(cpart);
        if (lane == 0) s_cred[w] = cpart;
        __syncthreads();
        if (tid == 0) {
            float v = 0.0f, cs = 0.0f;
#pragma unroll
            for (int i = 0; i < EWPB; i++) { v += s_fred[i]; cs += s_cred[i]; }
            float avg_ent = -v;
            float pse_m   = __ldcg(&g_pse_sum) * (1.0f / (float)NPIX);
            float commit  = 0.25f * cs * (1.0f / (float)NELEM);
            float ent_l   = 0.1f * (pse_m - avg_ent);
            out[OUT_SCALARS + 0] = commit + ent_l;   // loss
            out[OUT_SCALARS + 1] = commit;           // commitment_loss
            out[OUT_SCALARS + 2] = ent_l;            // entropy_loss
            out[OUT_SCALARS + 3] = pse_m;            // per_sample_entropy
            out[OUT_SCALARS + 4] = avg_ent;          // avg_entropy
        }
        // reset scratch for next graph replay
        for (int i = tid; i < NCODE; i += ETHR) __stcg(&g_avg_probs[i], 0.0f);
        if (tid == 0) {
            __stcg(&g_pse_sum, 0.0f);
            __threadfence();
            atomicExch(&g_done, 0u);
        }
    }
}

// ---------------------------------------------------------------------------
extern "C" void kernel_launch(void* const* d_in, const int* in_sizes, int n_in,
                              void* d_out, int out_size)
{
    const float* z   = (const float*)d_in[0];
    float*       out = (float*)d_out;
    (void)in_sizes; (void)n_in; (void)out_size;  // codebook implicit

    lfq_signidx_kernel<<<ABLK, ATHR>>>(z, out);
    lfq_entropy_kernel<<<EBLK, ETHR>>>(z, out);
}